// round 14
// baseline (speedup 1.0000x reference)
#include <cuda_runtime.h>
#include <cuda_bf16.h>
#include <math.h>

#define BN 64
#define SN 512
#define DN 768
#define HN 384
#define GN 1536
#define TN 22

// ---------------- scratch (static device globals; zero-initialized) ---------
__device__ __align__(256) __nv_bfloat16 g_eh[BN * SN * DN];   // embeds hi (bf16)
__device__ __align__(256) __nv_bfloat16 g_el[BN * SN * DN];   // embeds lo
__device__ __align__(256) __nv_bfloat16 g_Wh[2 * GN * DN];    // Wih hi, both dirs
__device__ __align__(256) __nv_bfloat16 g_Wl[2 * GN * DN];    // Wih lo
__device__ __align__(256) __nv_bfloat16 g_WhhH[2 * GN * HN];  // Whh hi, both dirs
__device__ __align__(256) __nv_bfloat16 g_WhhL[2 * GN * HN];  // Whh lo
__device__ __align__(256) __nv_bfloat16 g_hbH[2 * 2 * BN * HN]; // h hi [dir][par][b][k]
__device__ __align__(256) __nv_bfloat16 g_hbL[2 * 2 * BN * HN]; // h lo
__device__ float g_xg[2 * SN * BN * GN];                      // [dir][t][b][4H]
__device__ float g_lstm[BN * SN * 2 * HN];                    // [b][t][2H]
__device__ int   g_n[BN];
__device__ int   g_sent[BN];
__device__ int   g_last[BN];
__device__ unsigned g_bcnt[8];                                // monotonic, per (dir,bg)
__device__ unsigned g_bgen[8];

// ---------------- fast math helpers ---------------------------------------------
__device__ __forceinline__ float tanh_fast(float x) {
    float y;
    asm("tanh.approx.f32 %0, %1;" : "=f"(y) : "f"(x));
    return y;
}
__device__ __forceinline__ float sig_fast(float x) {
    return 0.5f * tanh_fast(0.5f * x) + 0.5f;
}

// bf16 mma: D += A(16x16,row) * B(16x8,col), fp32 accum
__device__ __forceinline__ void mma_bf16(float (&d)[4], const unsigned (&a)[4],
                                         unsigned b0, unsigned b1) {
    asm volatile(
        "mma.sync.aligned.m16n8k16.row.col.f32.bf16.bf16.f32 "
        "{%0,%1,%2,%3},{%4,%5,%6,%7},{%8,%9},{%0,%1,%2,%3};"
        : "+f"(d[0]), "+f"(d[1]), "+f"(d[2]), "+f"(d[3])
        : "r"(a[0]), "r"(a[1]), "r"(a[2]), "r"(a[3]), "r"(b0), "r"(b1));
}

// ---------------- scoped atomics (lstm barrier) ---------------------------------
__device__ __forceinline__ unsigned atom_add_acqrel(unsigned* p, unsigned v) {
    unsigned old;
    asm volatile("atom.acq_rel.gpu.global.add.u32 %0, [%1], %2;"
                 : "=r"(old) : "l"(p), "r"(v) : "memory");
    return old;
}
__device__ __forceinline__ unsigned ld_acquire(unsigned* p) {
    unsigned v;
    asm volatile("ld.acquire.gpu.global.u32 %0, [%1];" : "=r"(v) : "l"(p) : "memory");
    return v;
}
__device__ __forceinline__ void st_release_u32(unsigned* p, unsigned v) {
    asm volatile("st.release.gpu.global.u32 [%0], %1;" :: "l"(p), "r"(v) : "memory");
}

// ---------------- index helpers -------------------------------------------------
__device__ __forceinline__ long long ld_idx(const void* p, int i, bool is64) {
    return is64 ? ((const long long*)p)[i] : (long long)((const int*)p)[i];
}
__device__ __forceinline__ bool detect_is64(const void* start_ids) {
    return ((const int*)start_ids)[1] == 0;
}

// ---------------- K0: per-batch metadata ----------------------------------------
__global__ void meta_kernel(const void* start_ids, const void* masks) {
    int b = blockIdx.x;
    int tid = threadIdx.x;
    bool is64 = detect_is64(start_ids);
    __shared__ int red[256];
    int cnt = 0, sm = 0;
    for (int t = tid; t < SN; t += 256) {
        long long sv = ld_idx(start_ids, b * SN + t, is64);
        long long mv = ld_idx(masks, b * SN + t, is64);
        cnt += (sv >= 0);
        sm += (int)mv;
    }
    red[tid] = cnt; __syncthreads();
    for (int o = 128; o > 0; o >>= 1) { if (tid < o) red[tid] += red[tid + o]; __syncthreads(); }
    int ntot = red[0]; __syncthreads();
    red[tid] = sm; __syncthreads();
    for (int o = 128; o > 0; o >>= 1) { if (tid < o) red[tid] += red[tid + o]; __syncthreads(); }
    int stot = red[0];
    if (tid == 0) {
        g_n[b] = ntot;
        g_sent[b] = stot;
        long long last = 0;
        if (ntot > 0) last = ld_idx(start_ids, b * SN + ntot - 1, is64);
        g_last[b] = (int)last;
    }
}

// ---------------- K1: align gather + bf16 hi/lo split ----------------------------
__global__ void gather_kernel(const float* __restrict__ hs, const void* __restrict__ start_ids) {
    int t = blockIdx.x, b = blockIdx.y;
    int sent = g_sent[b];
    if (t >= sent) return;
    bool is64 = detect_is64(start_ids);
    int n = g_n[b];
    long long idx;
    if (t == 0)      idx = 0;
    else if (t < n)  idx = ld_idx(start_ids, b * SN + t, is64) - 1;
    else if (t == n) idx = g_last[b];
    else             idx = 0;
    if (idx < 0) idx = 0;
    if (idx > SN - 1) idx = SN - 1;
    const float4* src = (const float4*)(hs + ((size_t)b * SN + (size_t)idx) * DN);
    float4 v = src[threadIdx.x];
    size_t base = ((size_t)b * SN + t) * DN + threadIdx.x * 4;
    float e[4] = {v.x, v.y, v.z, v.w};
    __nv_bfloat16 h4[4], l4[4];
    #pragma unroll
    for (int i = 0; i < 4; i++) {
        h4[i] = __float2bfloat16(e[i]);
        l4[i] = __float2bfloat16(e[i] - __bfloat162float(h4[i]));
    }
    *(__nv_bfloat162*)&g_eh[base]     = __nv_bfloat162(h4[0], h4[1]);
    *(__nv_bfloat162*)&g_eh[base + 2] = __nv_bfloat162(h4[2], h4[3]);
    *(__nv_bfloat162*)&g_el[base]     = __nv_bfloat162(l4[0], l4[1]);
    *(__nv_bfloat162*)&g_el[base + 2] = __nv_bfloat162(l4[2], l4[3]);
}

// ---------------- K1b: Wih hi/lo split -------------------------------------------
__global__ void wconv_kernel(const float* __restrict__ Wf, const float* __restrict__ Wb) {
    int idx = (blockIdx.x * 256 + threadIdx.x) * 4;
    const int half = GN * DN;
    const float* src = (idx < half) ? (Wf + idx) : (Wb + (idx - half));
    float4 v = *(const float4*)src;
    float e[4] = {v.x, v.y, v.z, v.w};
    #pragma unroll
    for (int i = 0; i < 4; i++) {
        __nv_bfloat16 h = __float2bfloat16(e[i]);
        g_Wh[idx + i] = h;
        g_Wl[idx + i] = __float2bfloat16(e[i] - __bfloat162float(h));
    }
}

// ---------------- K1c: Whh hi/lo split -------------------------------------------
__global__ void wconv_hh_kernel(const float* __restrict__ Wf, const float* __restrict__ Wb) {
    int idx = (blockIdx.x * 256 + threadIdx.x) * 4;
    const int half = GN * HN;
    const float* src = (idx < half) ? (Wf + idx) : (Wb + (idx - half));
    float4 v = *(const float4*)src;
    float e[4] = {v.x, v.y, v.z, v.w};
    #pragma unroll
    for (int i = 0; i < 4; i++) {
        __nv_bfloat16 h = __float2bfloat16(e[i]);
        g_WhhH[idx + i] = h;
        g_WhhL[idx + i] = __float2bfloat16(e[i] - __bfloat162float(h));
    }
}

// ---------------- K2: input projection via bf16 split-3 tensor-core GEMM ---------
__global__ void __launch_bounds__(256, 2) projmma_kernel(
    const float* __restrict__ bihf, const float* __restrict__ bhhf,
    const float* __restrict__ bihb, const float* __restrict__ bhhb)
{
    int b = blockIdx.z & 63;
    int dir = blockIdx.z >> 6;
    int sent = g_sent[b];
    int t0 = blockIdx.y * 64;
    if (t0 >= sent) return;
    int n0 = blockIdx.x * 128;

    const float* bih = dir ? bihb : bihf;
    const float* bhh = dir ? bhhb : bhhf;

    extern __shared__ __nv_bfloat16 smb[];

    int tid = threadIdx.x;
    int warp = tid >> 5, lane = tid & 31;
    int wm = warp >> 2, wn = warp & 3;
    int g = lane >> 2, tig = lane & 3;

    float d[2][4][4];
    #pragma unroll
    for (int mt = 0; mt < 2; mt++)
        #pragma unroll
        for (int f = 0; f < 4; f++)
            #pragma unroll
            for (int c = 0; c < 4; c++) d[mt][f][c] = 0.f;

    const __nv_bfloat16* Eh = g_eh + ((size_t)b * SN + t0) * DN;
    const __nv_bfloat16* El = g_el + ((size_t)b * SN + t0) * DN;
    const __nv_bfloat16* Wh = g_Wh + ((size_t)dir * GN + n0) * DN;
    const __nv_bfloat16* Wl = g_Wl + ((size_t)dir * GN + n0) * DN;

    #define PJ_FILL(stg, k0)                                                              \
        do {                                                                              \
            __nv_bfloat16* S = smb + (stg) * 15360;                                       \
            {                                                                             \
                int row = tid >> 2, seg = tid & 3;                                        \
                unsigned da = (unsigned)__cvta_generic_to_shared(S + row * 40 + seg * 8); \
                asm volatile("cp.async.ca.shared.global [%0], [%1], 16;"                  \
                             :: "r"(da), "l"(Eh + (size_t)row * DN + (k0) + seg * 8));    \
                unsigned db = (unsigned)__cvta_generic_to_shared(S + 2560 + row * 40 + seg * 8); \
                asm volatile("cp.async.ca.shared.global [%0], [%1], 16;"                  \
                             :: "r"(db), "l"(El + (size_t)row * DN + (k0) + seg * 8));    \
            }                                                                             \
            _Pragma("unroll")                                                             \
            for (int jj = 0; jj < 2; jj++) {                                              \
                int i2 = tid + jj * 256;                                                  \
                int row = i2 >> 2, seg = i2 & 3;                                          \
                unsigned dc = (unsigned)__cvta_generic_to_shared(S + 5120 + row * 40 + seg * 8); \
                asm volatile("cp.async.ca.shared.global [%0], [%1], 16;"                  \
                             :: "r"(dc), "l"(Wh + (size_t)row * DN + (k0) + seg * 8));    \
                unsigned dd = (unsigned)__cvta_generic_to_shared(S + 10240 + row * 40 + seg * 8); \
                asm volatile("cp.async.ca.shared.global [%0], [%1], 16;"                  \
                             :: "r"(dd), "l"(Wl + (size_t)row * DN + (k0) + seg * 8));    \
            }                                                                             \
            asm volatile("cp.async.commit_group;");                                       \
        } while (0)

    PJ_FILL(0, 0);
    int st = 0;
    for (int k0 = 0; k0 < DN; k0 += 32) {
        if (k0 + 32 < DN) {
            PJ_FILL(st ^ 1, k0 + 32);
            asm volatile("cp.async.wait_group 1;");
        } else {
            asm volatile("cp.async.wait_group 0;");
        }
        __syncthreads();

        const __nv_bfloat16* S = smb + st * 15360;
        const unsigned* Ah = (const unsigned*)(S);
        const unsigned* Al = (const unsigned*)(S + 2560);
        const unsigned* Bh = (const unsigned*)(S + 5120);
        const unsigned* Bl = (const unsigned*)(S + 10240);

        #pragma unroll
        for (int s16 = 0; s16 < 2; s16++) {
            int kk = s16 * 8 + tig;
            unsigned ah[2][4], al[2][4];
            #pragma unroll
            for (int mt = 0; mt < 2; mt++) {
                int r = wm * 32 + mt * 16 + g;
                ah[mt][0] = Ah[r * 20 + kk];       ah[mt][1] = Ah[(r + 8) * 20 + kk];
                ah[mt][2] = Ah[r * 20 + kk + 4];   ah[mt][3] = Ah[(r + 8) * 20 + kk + 4];
                al[mt][0] = Al[r * 20 + kk];       al[mt][1] = Al[(r + 8) * 20 + kk];
                al[mt][2] = Al[r * 20 + kk + 4];   al[mt][3] = Al[(r + 8) * 20 + kk + 4];
            }
            #pragma unroll
            for (int f = 0; f < 4; f++) {
                int c = wn * 32 + f * 8 + g;
                unsigned bh0 = Bh[c * 20 + kk], bh1 = Bh[c * 20 + kk + 4];
                unsigned bl0 = Bl[c * 20 + kk], bl1 = Bl[c * 20 + kk + 4];
                #pragma unroll
                for (int mt = 0; mt < 2; mt++) {
                    mma_bf16(d[mt][f], ah[mt], bh0, bh1);
                    mma_bf16(d[mt][f], ah[mt], bl0, bl1);
                    mma_bf16(d[mt][f], al[mt], bh0, bh1);
                }
            }
        }
        __syncthreads();
        st ^= 1;
    }
    #undef PJ_FILL

    #pragma unroll
    for (int f = 0; f < 4; f++) {
        int n = n0 + wn * 32 + f * 8 + 2 * tig;
        float bs0 = bih[n] + bhh[n];
        float bs1 = bih[n + 1] + bhh[n + 1];
        #pragma unroll
        for (int mt = 0; mt < 2; mt++) {
            int r0 = t0 + wm * 32 + mt * 16 + g;
            if (r0 < sent) {
                float2 v = make_float2(d[mt][f][0] + bs0, d[mt][f][1] + bs1);
                *(float2*)&g_xg[((size_t)(dir * SN + r0) * BN + b) * GN + n] = v;
            }
            int r1 = r0 + 8;
            if (r1 < sent) {
                float2 v = make_float2(d[mt][f][2] + bs0, d[mt][f][3] + bs1);
                *(float2*)&g_xg[((size_t)(dir * SN + r1) * BN + b) * GN + n] = v;
            }
        }
    }
}

// ---------------- K3: persistent LSTM, tensor-core recurrence, 24-unit slices -----
// 128 blocks, 1/SM. dir = blk>>6; r6 = blk&63; bg = r6>>4 (16 batches);
// u0 = (r6&15)*24 (24 hidden units = 96 gate rows). Groups of 16 blocks per
// (dir,bg) -> 16-arrival barrier (halved convoy vs R12). Whh slice bf16 hi/lo in
// smem (96 x 392); warps 0-5 do mma (16 gate rows each, full K=384, split-3).
__global__ void __launch_bounds__(256, 1) lstm_kernel(
    const float* __restrict__ bihf, const float* __restrict__ bhhf,
    const float* __restrict__ bihb, const float* __restrict__ bhhb,
    const float* __restrict__ h0, const float* __restrict__ c0)
{
    extern __shared__ char smc[];
    __nv_bfloat16* BhS = (__nv_bfloat16*)smc;                   // 96*392*2 = 75264 B
    __nv_bfloat16* BlS = (__nv_bfloat16*)(smc + 75264);         // 75264 B
    __nv_bfloat16* AhS = (__nv_bfloat16*)(smc + 150528);        // 16*392*2 = 12544 B
    __nv_bfloat16* AlS = (__nv_bfloat16*)(smc + 163072);        // 12544 B
    float* P      = (float*)(smc + 175616);                     // 96*17*4 = 6528 B
    float* bias_s = (float*)(smc + 182144);                     // 96*4
    int*   sent_s = (int*)(smc + 182528);                       // 16*4 (end 182592)

    int tid = threadIdx.x;
    int blk = blockIdx.x;
    int dir = blk >> 6;
    int r6  = blk & 63;
    int bg  = r6 >> 4;
    int u0  = (r6 & 15) * 24;

    const float* bih = dir ? bihb : bihf;
    const float* bhh = dir ? bhhb : bhhf;

    // one-time: Whh slice (hi/lo) into smem, stride 392 bf16
    {
        const __nv_bfloat16* WH = g_WhhH + (size_t)dir * GN * HN;
        const __nv_bfloat16* WL = g_WhhL + (size_t)dir * GN * HN;
        for (int i = tid; i < 96 * 48; i += 256) {
            int r = i / 48, c = i % 48;
            int grow = (r / 24) * HN + u0 + (r % 24);
            unsigned dh = (unsigned)__cvta_generic_to_shared(BhS + r * 392 + c * 8);
            asm volatile("cp.async.ca.shared.global [%0], [%1], 16;"
                         :: "r"(dh), "l"(WH + (size_t)grow * HN + c * 8));
            unsigned dl = (unsigned)__cvta_generic_to_shared(BlS + r * 392 + c * 8);
            asm volatile("cp.async.ca.shared.global [%0], [%1], 16;"
                         :: "r"(dl), "l"(WL + (size_t)grow * HN + c * 8));
        }
        asm volatile("cp.async.commit_group;");
    }
    if (tid < 96) {
        int grow = (tid / 24) * HN + u0 + (tid % 24);
        bias_s[tid] = bih[grow] + bhh[grow];
    }
    if (tid < 16) sent_s[tid] = g_sent[bg * 16 + tid];

    // cell ownership: 384 elements over 256 threads: e0 = tid, e1 = tid + 256 (tid<128)
    int lb0 = tid / 24, u0e = tid % 24;
    int gb0 = bg * 16 + lb0, gj0 = u0 + u0e;
    bool e1v = (tid < 128);
    int e1 = tid + 256;
    int lb1 = e1 / 24, u1e = e1 % 24;
    int gb1 = bg * 16 + lb1, gj1 = u0 + u1e;

    float creg0, creg1 = 0.f;
    {
        float h0v = h0[((size_t)dir * BN + gb0) * HN + gj0];
        __nv_bfloat16 hh = __float2bfloat16(h0v);
        g_hbH[((dir * 2 + 0) * BN + gb0) * HN + gj0] = hh;
        g_hbL[((dir * 2 + 0) * BN + gb0) * HN + gj0] =
            __float2bfloat16(h0v - __bfloat162float(hh));
        creg0 = c0[((size_t)dir * BN + gb0) * HN + gj0];
    }
    if (e1v) {
        float h0v = h0[((size_t)dir * BN + gb1) * HN + gj1];
        __nv_bfloat16 hh = __float2bfloat16(h0v);
        g_hbH[((dir * 2 + 0) * BN + gb1) * HN + gj1] = hh;
        g_hbL[((dir * 2 + 0) * BN + gb1) * HN + gj1] =
            __float2bfloat16(h0v - __bfloat162float(hh));
        creg1 = c0[((size_t)dir * BN + gb1) * HN + gj1];
    }

    int warp = tid >> 5, lane = tid & 31;
    int g = lane >> 2, tig = lane & 3;

    asm volatile("cp.async.wait_group 0;");

    int gid = dir * 4 + bg;
    unsigned my_gen = 0;
    if (tid == 0) my_gen = ld_acquire(&g_bgen[gid]);
    __syncthreads();
    if (tid == 0) {
        __threadfence();
        unsigned old = atom_add_acqrel(&g_bcnt[gid], 1u);
        if (((old + 1) & 15u) == 0u) st_release_u32(&g_bgen[gid], my_gen + 1);
        else while (ld_acquire(&g_bgen[gid]) == my_gen) { }
        my_gen++;
    }
    __syncthreads();

    for (int s = 0; s < SN; s++) {
        int p = s & 1;
        int t = dir ? (SN - 1 - s) : s;

        // stage h (hi/lo) for our 16 batches: 768 chunks/array, 3 per thread each
        {
            const __nv_bfloat16* hH = g_hbH + (size_t)((dir * 2 + p) * BN + bg * 16) * HN;
            const __nv_bfloat16* hL = g_hbL + (size_t)((dir * 2 + p) * BN + bg * 16) * HN;
            #pragma unroll
            for (int f = 0; f < 3; f++) {
                int i2 = tid + f * 256;
                int row = i2 / 48, c = i2 % 48;
                unsigned dh = (unsigned)__cvta_generic_to_shared(AhS + row * 392 + c * 8);
                asm volatile("cp.async.cg.shared.global [%0], [%1], 16;"
                             :: "r"(dh), "l"(hH + (size_t)row * HN + c * 8));
                unsigned dl = (unsigned)__cvta_generic_to_shared(AlS + row * 392 + c * 8);
                asm volatile("cp.async.cg.shared.global [%0], [%1], 16;"
                             :: "r"(dl), "l"(hL + (size_t)row * HN + c * 8));
            }
            asm volatile("cp.async.commit_group;");
        }

        // prefetch xg for both cell elements
        float xp0[4], xp1[4];
        {
            const float* xb = &g_xg[((size_t)(dir * SN + t) * BN + gb0) * GN + gj0];
            #pragma unroll
            for (int g2 = 0; g2 < 4; g2++) xp0[g2] = xb[g2 * HN];
        }
        if (e1v) {
            const float* xb = &g_xg[((size_t)(dir * SN + t) * BN + gb1) * GN + gj1];
            #pragma unroll
            for (int g2 = 0; g2 < 4; g2++) xp1[g2] = xb[g2 * HN];
        }

        asm volatile("cp.async.wait_group 0;");
        __syncthreads();

        // mma: warps 0-5, each 16 gate rows (2 n-tiles), full K=384 (24 k-steps)
        if (warp < 6) {
            const unsigned* Ah = (const unsigned*)AhS;
            const unsigned* Al = (const unsigned*)AlS;
            const unsigned* Bh = (const unsigned*)BhS;
            const unsigned* Bl = (const unsigned*)BlS;
            int baseA0 = g * 196, baseA1 = (g + 8) * 196;
            int baseB0 = (warp * 16 + g) * 196;
            int baseB1 = (warp * 16 + 8 + g) * 196;

            float d0[4] = {0.f, 0.f, 0.f, 0.f};
            float d1[4] = {0.f, 0.f, 0.f, 0.f};
            #pragma unroll 4
            for (int kt = 0; kt < 24; kt++) {
                int kk = kt * 8 + tig;
                unsigned ah[4] = {Ah[baseA0 + kk], Ah[baseA1 + kk],
                                  Ah[baseA0 + kk + 4], Ah[baseA1 + kk + 4]};
                unsigned al[4] = {Al[baseA0 + kk], Al[baseA1 + kk],
                                  Al[baseA0 + kk + 4], Al[baseA1 + kk + 4]};
                unsigned bh00 = Bh[baseB0 + kk], bh01 = Bh[baseB0 + kk + 4];
                unsigned bh10 = Bh[baseB1 + kk], bh11 = Bh[baseB1 + kk + 4];
                unsigned bl00 = Bl[baseB0 + kk], bl01 = Bl[baseB0 + kk + 4];
                unsigned bl10 = Bl[baseB1 + kk], bl11 = Bl[baseB1 + kk + 4];
                mma_bf16(d0, ah, bh00, bh01);
                mma_bf16(d0, ah, bl00, bl01);
                mma_bf16(d0, al, bh00, bh01);
                mma_bf16(d1, ah, bh10, bh11);
                mma_bf16(d1, ah, bl10, bl11);
                mma_bf16(d1, al, bh10, bh11);
            }
            int rb0 = warp * 16 + 2 * tig;
            P[(rb0 + 0) * 17 + g]     = d0[0];
            P[(rb0 + 1) * 17 + g]     = d0[1];
            P[(rb0 + 0) * 17 + g + 8] = d0[2];
            P[(rb0 + 1) * 17 + g + 8] = d0[3];
            int rb1 = rb0 + 8;
            P[(rb1 + 0) * 17 + g]     = d1[0];
            P[(rb1 + 1) * 17 + g]     = d1[1];
            P[(rb1 + 0) * 17 + g + 8] = d1[2];
            P[(rb1 + 1) * 17 + g + 8] = d1[3];
        }
        __syncthreads();

        // cell update (element 0, and element 1 for tid<128)
        float hv0, hv1 = 0.f;
        {
            bool valid = (t < sent_s[lb0]);
            float g4[4];
            #pragma unroll
            for (int g2 = 0; g2 < 4; g2++) {
                int r = g2 * 24 + u0e;
                g4[g2] = P[r * 17 + lb0] + (valid ? xp0[g2] : bias_s[r]);
            }
            float ig = sig_fast(g4[0]), fg = sig_fast(g4[1]);
            float cg = tanh_fast(g4[2]), og = sig_fast(g4[3]);
            creg0 = fg * creg0 + ig * cg;
            hv0 = og * tanh_fast(creg0);
            __nv_bfloat16 hh = __float2bfloat16(hv0);
            size_t ho = (size_t)((dir * 2 + (p ^ 1)) * BN + gb0) * HN + gj0;
            g_hbH[ho] = hh;
            g_hbL[ho] = __float2bfloat16(hv0 - __bfloat162float(hh));
        }
        if (e1v) {
            bool valid = (t < sent_s[lb1]);
            float g4[4];
            #pragma unroll
            for (int g2 = 0; g2 < 4; g2++) {
                int r = g2 * 24 + u1e;
                g4[g2] = P[r * 17 + lb1] + (valid ? xp1[g2] : bias_s[r]);
            }
            float ig = sig_fast(g4[0]), fg = sig_fast(g4[1]);
            float cg = tanh_fast(g4[2]), og = sig_fast(g4[3]);
            creg1 = fg * creg1 + ig * cg;
            hv1 = og * tanh_fast(creg1);
            __nv_bfloat16 hh = __float2bfloat16(hv1);
            size_t ho = (size_t)((dir * 2 + (p ^ 1)) * BN + gb1) * HN + gj1;
            g_hbH[ho] = hh;
            g_hbL[ho] = __float2bfloat16(hv1 - __bfloat162float(hh));
        }
        __syncthreads();

        if (tid == 0) {
            __threadfence();
            unsigned old = atom_add_acqrel(&g_bcnt[gid], 1u);
            if (((old + 1) & 15u) == 0u) st_release_u32(&g_bgen[gid], my_gen + 1);
        }
        // g_lstm stores hidden under the barrier wait
        g_lstm[((size_t)gb0 * SN + t) * (2 * HN) + dir * HN + gj0] = hv0;
        if (e1v)
            g_lstm[((size_t)gb1 * SN + t) * (2 * HN) + dir * HN + gj1] = hv1;
        if (tid == 0) {
            while (ld_acquire(&g_bgen[gid]) == my_gen) { }
            my_gen++;
        }
        __syncthreads();
    }
}

// ---------------- K4: output linear (Wlin cached in smem, 16 rows/block) ----------
__global__ void __launch_bounds__(256) out_kernel(
    const float* __restrict__ Wlin, const float* __restrict__ blin,
    float* __restrict__ out)
{
    extern __shared__ float Wl[];
    int tid = threadIdx.x;
    int lane = tid & 31, w = tid >> 5;
    for (int idx = tid; idx < TN * 768; idx += 256) Wl[idx] = Wlin[idx];
    __syncthreads();

    int base = blockIdx.x * 16;
    #pragma unroll
    for (int rr = 0; rr < 2; rr++) {
        int row = base + w * 2 + rr;
        const float* src = g_lstm + (size_t)row * 768;
        float rs[24];
        #pragma unroll
        for (int i = 0; i < 24; i++) rs[i] = src[lane + 32 * i];
        for (int o = 0; o < TN; o++) {
            const float* wr = &Wl[o * 768];
            float s = 0.f;
            #pragma unroll
            for (int i = 0; i < 24; i++) s += rs[i] * wr[lane + 32 * i];
            #pragma unroll
            for (int off = 16; off; off >>= 1) s += __shfl_down_sync(0xffffffffu, s, off);
            if (lane == 0) out[(size_t)row * TN + o] = s + blin[o];
        }
    }
}

// ---------------- launch -----------------------------------------------------------
extern "C" void kernel_launch(void* const* d_in, const int* in_sizes, int n_in,
                              void* d_out, int out_size) {
    const float* hs   = (const float*)d_in[0];
    const float* h0   = (const float*)d_in[1];
    const float* c0   = (const float*)d_in[2];
    const float* Wihf = (const float*)d_in[3];
    const float* Whhf = (const float*)d_in[4];
    const float* bihf = (const float*)d_in[5];
    const float* bhhf = (const float*)d_in[6];
    const float* Wihb = (const float*)d_in[7];
    const float* Whhb = (const float*)d_in[8];
    const float* bihb = (const float*)d_in[9];
    const float* bhhb = (const float*)d_in[10];
    const float* Wlin = (const float*)d_in[11];
    const float* blin = (const float*)d_in[12];
    const void*  sid  = d_in[13];
    const void*  msk  = d_in[14];

    meta_kernel<<<BN, 256>>>(sid, msk);
    gather_kernel<<<dim3(SN, BN), 192>>>(hs, sid);
    wconv_kernel<<<(2 * GN * DN) / (256 * 4), 256>>>(Wihf, Wihb);
    wconv_hh_kernel<<<(2 * GN * HN) / (256 * 4), 256>>>(Whhf, Whhb);

    const int pj_smem = 2 * 15360 * 2;   // 61,440 B
    cudaFuncSetAttribute(projmma_kernel, cudaFuncAttributeMaxDynamicSharedMemorySize, pj_smem);
    projmma_kernel<<<dim3(GN / 128, SN / 64, 2 * BN), 256, pj_smem>>>(bihf, bhhf, bihb, bhhb);

    const int rec_smem = 182592;
    cudaFuncSetAttribute(lstm_kernel, cudaFuncAttributeMaxDynamicSharedMemorySize, rec_smem);
    lstm_kernel<<<128, 256, rec_smem>>>(bihf, bhhf, bihb, bhhb, h0, c0);

    const int out_smem = TN * 768 * 4;
    cudaFuncSetAttribute(out_kernel, cudaFuncAttributeMaxDynamicSharedMemorySize, out_smem);
    out_kernel<<<(BN * SN) / 16, 256, out_smem>>>(Wlin, blin, (float*)d_out);
}

// round 15
// speedup vs baseline: 1.0514x; 1.0514x over previous
#include <cuda_runtime.h>
#include <cuda_bf16.h>
#include <math.h>

#define BN 64
#define SN 512
#define DN 768
#define HN 384
#define GN 1536
#define TN 22

// ---------------- scratch (static device globals; zero-initialized) ---------
__device__ __align__(256) __nv_bfloat16 g_eh[BN * SN * DN];   // embeds hi (bf16)
__device__ __align__(256) __nv_bfloat16 g_el[BN * SN * DN];   // embeds lo
__device__ __align__(256) __nv_bfloat16 g_Wh[2 * GN * DN];    // Wih hi, both dirs
__device__ __align__(256) __nv_bfloat16 g_Wl[2 * GN * DN];    // Wih lo
__device__ __align__(256) __nv_bfloat16 g_WhhH[2 * GN * HN];  // Whh hi, both dirs
__device__ __align__(256) __nv_bfloat16 g_WhhL[2 * GN * HN];  // Whh lo
__device__ __align__(256) __nv_bfloat16 g_hbH[2 * 2 * BN * HN]; // h hi [dir][par][b][k]
__device__ __align__(256) __nv_bfloat16 g_hbL[2 * 2 * BN * HN]; // h lo
__device__ float g_xg[2 * SN * BN * GN];                      // [dir][t][b][4H]
__device__ float g_lstm[BN * SN * 2 * HN];                    // [b][t][2H]
__device__ int   g_n[BN];
__device__ int   g_sent[BN];
__device__ int   g_last[BN];
__device__ unsigned g_bcnt[8];                                // monotonic, per (dir,bg)
__device__ unsigned g_bgen[8];

// ---------------- fast math helpers ---------------------------------------------
__device__ __forceinline__ float tanh_fast(float x) {
    float y;
    asm("tanh.approx.f32 %0, %1;" : "=f"(y) : "f"(x));
    return y;
}
__device__ __forceinline__ float sig_fast(float x) {
    return 0.5f * tanh_fast(0.5f * x) + 0.5f;
}

// bf16 mma: D += A(16x16,row) * B(16x8,col), fp32 accum
__device__ __forceinline__ void mma_bf16(float (&d)[4], const unsigned (&a)[4],
                                         unsigned b0, unsigned b1) {
    asm volatile(
        "mma.sync.aligned.m16n8k16.row.col.f32.bf16.bf16.f32 "
        "{%0,%1,%2,%3},{%4,%5,%6,%7},{%8,%9},{%0,%1,%2,%3};"
        : "+f"(d[0]), "+f"(d[1]), "+f"(d[2]), "+f"(d[3])
        : "r"(a[0]), "r"(a[1]), "r"(a[2]), "r"(a[3]), "r"(b0), "r"(b1));
}

// ldmatrix x4 (b16): 4 8x8 tiles, octet-addressed
__device__ __forceinline__ void ldsm_x4(unsigned (&r)[4], unsigned saddr) {
    asm volatile("ldmatrix.sync.aligned.m8n8.x4.shared.b16 {%0,%1,%2,%3}, [%4];"
                 : "=r"(r[0]), "=r"(r[1]), "=r"(r[2]), "=r"(r[3]) : "r"(saddr));
}

// ---------------- scoped atomics (lstm barrier) ---------------------------------
__device__ __forceinline__ unsigned atom_add_acqrel(unsigned* p, unsigned v) {
    unsigned old;
    asm volatile("atom.acq_rel.gpu.global.add.u32 %0, [%1], %2;"
                 : "=r"(old) : "l"(p), "r"(v) : "memory");
    return old;
}
__device__ __forceinline__ unsigned ld_acquire(unsigned* p) {
    unsigned v;
    asm volatile("ld.acquire.gpu.global.u32 %0, [%1];" : "=r"(v) : "l"(p) : "memory");
    return v;
}
__device__ __forceinline__ void st_release_u32(unsigned* p, unsigned v) {
    asm volatile("st.release.gpu.global.u32 [%0], %1;" :: "l"(p), "r"(v) : "memory");
}

// ---------------- index helpers -------------------------------------------------
__device__ __forceinline__ long long ld_idx(const void* p, int i, bool is64) {
    return is64 ? ((const long long*)p)[i] : (long long)((const int*)p)[i];
}
__device__ __forceinline__ bool detect_is64(const void* start_ids) {
    return ((const int*)start_ids)[1] == 0;
}

// ---------------- K0: per-batch metadata ----------------------------------------
__global__ void meta_kernel(const void* start_ids, const void* masks) {
    int b = blockIdx.x;
    int tid = threadIdx.x;
    bool is64 = detect_is64(start_ids);
    __shared__ int red[256];
    int cnt = 0, sm = 0;
    for (int t = tid; t < SN; t += 256) {
        long long sv = ld_idx(start_ids, b * SN + t, is64);
        long long mv = ld_idx(masks, b * SN + t, is64);
        cnt += (sv >= 0);
        sm += (int)mv;
    }
    red[tid] = cnt; __syncthreads();
    for (int o = 128; o > 0; o >>= 1) { if (tid < o) red[tid] += red[tid + o]; __syncthreads(); }
    int ntot = red[0]; __syncthreads();
    red[tid] = sm; __syncthreads();
    for (int o = 128; o > 0; o >>= 1) { if (tid < o) red[tid] += red[tid + o]; __syncthreads(); }
    int stot = red[0];
    if (tid == 0) {
        g_n[b] = ntot;
        g_sent[b] = stot;
        long long last = 0;
        if (ntot > 0) last = ld_idx(start_ids, b * SN + ntot - 1, is64);
        g_last[b] = (int)last;
    }
}

// ---------------- K1: align gather + bf16 hi/lo split ----------------------------
__global__ void gather_kernel(const float* __restrict__ hs, const void* __restrict__ start_ids) {
    int t = blockIdx.x, b = blockIdx.y;
    int sent = g_sent[b];
    if (t >= sent) return;
    bool is64 = detect_is64(start_ids);
    int n = g_n[b];
    long long idx;
    if (t == 0)      idx = 0;
    else if (t < n)  idx = ld_idx(start_ids, b * SN + t, is64) - 1;
    else if (t == n) idx = g_last[b];
    else             idx = 0;
    if (idx < 0) idx = 0;
    if (idx > SN - 1) idx = SN - 1;
    const float4* src = (const float4*)(hs + ((size_t)b * SN + (size_t)idx) * DN);
    float4 v = src[threadIdx.x];
    size_t base = ((size_t)b * SN + t) * DN + threadIdx.x * 4;
    float e[4] = {v.x, v.y, v.z, v.w};
    __nv_bfloat16 h4[4], l4[4];
    #pragma unroll
    for (int i = 0; i < 4; i++) {
        h4[i] = __float2bfloat16(e[i]);
        l4[i] = __float2bfloat16(e[i] - __bfloat162float(h4[i]));
    }
    *(__nv_bfloat162*)&g_eh[base]     = __nv_bfloat162(h4[0], h4[1]);
    *(__nv_bfloat162*)&g_eh[base + 2] = __nv_bfloat162(h4[2], h4[3]);
    *(__nv_bfloat162*)&g_el[base]     = __nv_bfloat162(l4[0], l4[1]);
    *(__nv_bfloat162*)&g_el[base + 2] = __nv_bfloat162(l4[2], l4[3]);
}

// ---------------- K1b: Wih hi/lo split -------------------------------------------
__global__ void wconv_kernel(const float* __restrict__ Wf, const float* __restrict__ Wb) {
    int idx = (blockIdx.x * 256 + threadIdx.x) * 4;
    const int half = GN * DN;
    const float* src = (idx < half) ? (Wf + idx) : (Wb + (idx - half));
    float4 v = *(const float4*)src;
    float e[4] = {v.x, v.y, v.z, v.w};
    #pragma unroll
    for (int i = 0; i < 4; i++) {
        __nv_bfloat16 h = __float2bfloat16(e[i]);
        g_Wh[idx + i] = h;
        g_Wl[idx + i] = __float2bfloat16(e[i] - __bfloat162float(h));
    }
}

// ---------------- K1c: Whh hi/lo split -------------------------------------------
__global__ void wconv_hh_kernel(const float* __restrict__ Wf, const float* __restrict__ Wb) {
    int idx = (blockIdx.x * 256 + threadIdx.x) * 4;
    const int half = GN * HN;
    const float* src = (idx < half) ? (Wf + idx) : (Wb + (idx - half));
    float4 v = *(const float4*)src;
    float e[4] = {v.x, v.y, v.z, v.w};
    #pragma unroll
    for (int i = 0; i < 4; i++) {
        __nv_bfloat16 h = __float2bfloat16(e[i]);
        g_WhhH[idx + i] = h;
        g_WhhL[idx + i] = __float2bfloat16(e[i] - __bfloat162float(h));
    }
}

// ---------------- K2: input projection, split-3 bf16 mma + ldmatrix --------------
// Block tile 64(t) x 128(n), 8 warps (2m x 4n), warp tile 32x32.
// Fragment loads via ldmatrix.x4: per k-stage 16 LDSM replace 64 scalar LDS.
__global__ void __launch_bounds__(256, 2) projmma_kernel(
    const float* __restrict__ bihf, const float* __restrict__ bhhf,
    const float* __restrict__ bihb, const float* __restrict__ bhhb)
{
    int b = blockIdx.z & 63;
    int dir = blockIdx.z >> 6;
    int sent = g_sent[b];
    int t0 = blockIdx.y * 64;
    if (t0 >= sent) return;
    int n0 = blockIdx.x * 128;

    const float* bih = dir ? bihb : bihf;
    const float* bhh = dir ? bhhb : bhhf;

    extern __shared__ __nv_bfloat16 smb[];
    // per stage (15360 bf16 = 30720 B): Ah @0B, Al @5120B, Bh @10240B, Bl @20480B

    int tid = threadIdx.x;
    int warp = tid >> 5, lane = tid & 31;
    int wm = warp >> 2, wn = warp & 3;
    int g = lane >> 2, tig = lane & 3;
    int lr = lane & 7, lq = lane >> 3;

    // ldmatrix per-lane byte offsets (within a stage)
    // A: octets = {rows-lo k-lo, rows-hi k-lo, rows-lo k-hi, rows-hi k-hi}
    unsigned aoff = ((wm * 32 + (lq & 1) * 8 + lr) * 40 + (lq >> 1) * 8) * 2;
    // B: octets = {f-even k-lo, f-even k-hi, f-odd k-lo, f-odd k-hi}
    unsigned boff = ((wn * 32 + (lq >> 1) * 8 + lr) * 40 + (lq & 1) * 8) * 2;
    unsigned smb_base = (unsigned)__cvta_generic_to_shared(smb);

    float d[2][4][4];
    #pragma unroll
    for (int mt = 0; mt < 2; mt++)
        #pragma unroll
        for (int f = 0; f < 4; f++)
            #pragma unroll
            for (int c = 0; c < 4; c++) d[mt][f][c] = 0.f;

    const __nv_bfloat16* Eh = g_eh + ((size_t)b * SN + t0) * DN;
    const __nv_bfloat16* El = g_el + ((size_t)b * SN + t0) * DN;
    const __nv_bfloat16* Wh = g_Wh + ((size_t)dir * GN + n0) * DN;
    const __nv_bfloat16* Wl = g_Wl + ((size_t)dir * GN + n0) * DN;

    #define PJ_FILL(stg, k0)                                                              \
        do {                                                                              \
            __nv_bfloat16* S = smb + (stg) * 15360;                                       \
            {                                                                             \
                int row = tid >> 2, seg = tid & 3;                                        \
                unsigned da = (unsigned)__cvta_generic_to_shared(S + row * 40 + seg * 8); \
                asm volatile("cp.async.ca.shared.global [%0], [%1], 16;"                  \
                             :: "r"(da), "l"(Eh + (size_t)row * DN + (k0) + seg * 8));    \
                unsigned db = (unsigned)__cvta_generic_to_shared(S + 2560 + row * 40 + seg * 8); \
                asm volatile("cp.async.ca.shared.global [%0], [%1], 16;"                  \
                             :: "r"(db), "l"(El + (size_t)row * DN + (k0) + seg * 8));    \
            }                                                                             \
            _Pragma("unroll")                                                             \
            for (int jj = 0; jj < 2; jj++) {                                              \
                int i2 = tid + jj * 256;                                                  \
                int row = i2 >> 2, seg = i2 & 3;                                          \
                unsigned dc = (unsigned)__cvta_generic_to_shared(S + 5120 + row * 40 + seg * 8); \
                asm volatile("cp.async.ca.shared.global [%0], [%1], 16;"                  \
                             :: "r"(dc), "l"(Wh + (size_t)row * DN + (k0) + seg * 8));    \
                unsigned dd = (unsigned)__cvta_generic_to_shared(S + 10240 + row * 40 + seg * 8); \
                asm volatile("cp.async.ca.shared.global [%0], [%1], 16;"                  \
                             :: "r"(dd), "l"(Wl + (size_t)row * DN + (k0) + seg * 8));    \
            }                                                                             \
            asm volatile("cp.async.commit_group;");                                      \
        } while (0)

    PJ_FILL(0, 0);
    int st = 0;
    for (int k0 = 0; k0 < DN; k0 += 32) {
        if (k0 + 32 < DN) {
            PJ_FILL(st ^ 1, k0 + 32);
            asm volatile("cp.async.wait_group 1;");
        } else {
            asm volatile("cp.async.wait_group 0;");
        }
        __syncthreads();

        unsigned sb = smb_base + st * 30720;

        #pragma unroll
        for (int s16 = 0; s16 < 2; s16++) {
            unsigned koff = s16 * 32;
            unsigned ah[2][4], al[2][4];
            #pragma unroll
            for (int mt = 0; mt < 2; mt++) {
                ldsm_x4(ah[mt], sb + aoff + mt * 1280 + koff);
                ldsm_x4(al[mt], sb + 5120 + aoff + mt * 1280 + koff);
            }
            #pragma unroll
            for (int fp = 0; fp < 2; fp++) {
                unsigned rb[4], rl[4];
                ldsm_x4(rb, sb + 10240 + boff + fp * 1280 + koff);
                ldsm_x4(rl, sb + 20480 + boff + fp * 1280 + koff);
                #pragma unroll
                for (int ff = 0; ff < 2; ff++) {
                    int f = fp * 2 + ff;
                    unsigned bh0 = rb[ff * 2], bh1 = rb[ff * 2 + 1];
                    unsigned bl0 = rl[ff * 2], bl1 = rl[ff * 2 + 1];
                    #pragma unroll
                    for (int mt = 0; mt < 2; mt++) {
                        mma_bf16(d[mt][f], ah[mt], bh0, bh1);
                        mma_bf16(d[mt][f], ah[mt], bl0, bl1);
                        mma_bf16(d[mt][f], al[mt], bh0, bh1);
                    }
                }
            }
        }
        __syncthreads();
        st ^= 1;
    }
    #undef PJ_FILL

    #pragma unroll
    for (int f = 0; f < 4; f++) {
        int n = n0 + wn * 32 + f * 8 + 2 * tig;
        float bs0 = bih[n] + bhh[n];
        float bs1 = bih[n + 1] + bhh[n + 1];
        #pragma unroll
        for (int mt = 0; mt < 2; mt++) {
            int r0 = t0 + wm * 32 + mt * 16 + g;
            if (r0 < sent) {
                float2 v = make_float2(d[mt][f][0] + bs0, d[mt][f][1] + bs1);
                *(float2*)&g_xg[((size_t)(dir * SN + r0) * BN + b) * GN + n] = v;
            }
            int r1 = r0 + 8;
            if (r1 < sent) {
                float2 v = make_float2(d[mt][f][2] + bs0, d[mt][f][3] + bs1);
                *(float2*)&g_xg[((size_t)(dir * SN + r1) * BN + b) * GN + n] = v;
            }
        }
    }
}

// ---------------- K3: persistent LSTM (proven R12 version, unchanged) -------------
// 256 blocks, 2/SM. dir = blk>>7; bg = (blk&127)>>5 (16 batches); u0 = (blk&31)*12
// (12 hidden units = 48 gate rows). P[16b x 48r] via split-3 bf16 mma (warps 0-2).
__global__ void __launch_bounds__(256, 2) lstm_kernel(
    const float* __restrict__ bihf, const float* __restrict__ bhhf,
    const float* __restrict__ bihb, const float* __restrict__ bhhb,
    const float* __restrict__ h0, const float* __restrict__ c0)
{
    extern __shared__ char smc[];
    __nv_bfloat16* BhS = (__nv_bfloat16*)smc;                   // 48*392 = 37632 B
    __nv_bfloat16* BlS = (__nv_bfloat16*)(smc + 37632);         // 37632 B
    __nv_bfloat16* AhS = (__nv_bfloat16*)(smc + 75264);         // 12544 B
    __nv_bfloat16* AlS = (__nv_bfloat16*)(smc + 87808);         // 12544 B
    float* P      = (float*)(smc + 100352);                     // 3264 B
    float* bias_s = (float*)(smc + 103616);                     // 192 B
    int*   sent_s = (int*)(smc + 103808);                       // 64 B (end 103872)

    int tid = threadIdx.x;
    int blk = blockIdx.x;
    int dir = blk >> 7;
    int r7  = blk & 127;
    int bg  = r7 >> 5;
    int u0  = (r7 & 31) * 12;

    const float* bih = dir ? bihb : bihf;
    const float* bhh = dir ? bhhb : bhhf;

    {
        const __nv_bfloat16* WH = g_WhhH + (size_t)dir * GN * HN;
        const __nv_bfloat16* WL = g_WhhL + (size_t)dir * GN * HN;
        for (int i = tid; i < 48 * 48; i += 256) {
            int r = i / 48, c = i % 48;
            int grow = (r / 12) * HN + u0 + (r % 12);
            unsigned dh = (unsigned)__cvta_generic_to_shared(BhS + r * 392 + c * 8);
            asm volatile("cp.async.ca.shared.global [%0], [%1], 16;"
                         :: "r"(dh), "l"(WH + (size_t)grow * HN + c * 8));
            unsigned dl = (unsigned)__cvta_generic_to_shared(BlS + r * 392 + c * 8);
            asm volatile("cp.async.ca.shared.global [%0], [%1], 16;"
                         :: "r"(dl), "l"(WL + (size_t)grow * HN + c * 8));
        }
        asm volatile("cp.async.commit_group;");
    }
    if (tid < 48) {
        int grow = (tid / 12) * HN + u0 + (tid % 12);
        bias_s[tid] = bih[grow] + bhh[grow];
    }
    if (tid < 16) sent_s[tid] = g_sent[bg * 16 + tid];

    bool cellv = (tid < 192);
    int lb = tid / 12, u = tid % 12;
    int gb = bg * 16 + lb;
    int gj = u0 + u;
    float creg = 0.f;
    if (cellv) {
        float h0v = h0[((size_t)dir * BN + gb) * HN + gj];
        __nv_bfloat16 hh = __float2bfloat16(h0v);
        g_hbH[((dir * 2 + 0) * BN + gb) * HN + gj] = hh;
        g_hbL[((dir * 2 + 0) * BN + gb) * HN + gj] =
            __float2bfloat16(h0v - __bfloat162float(hh));
        creg = c0[((size_t)dir * BN + gb) * HN + gj];
    }

    int warp = tid >> 5, lane = tid & 31;
    int g = lane >> 2, tig = lane & 3;

    asm volatile("cp.async.wait_group 0;");

    int gid = dir * 4 + bg;
    unsigned my_gen = 0;
    if (tid == 0) my_gen = ld_acquire(&g_bgen[gid]);
    __syncthreads();
    if (tid == 0) {
        __threadfence();
        unsigned old = atom_add_acqrel(&g_bcnt[gid], 1u);
        if (((old + 1) & 31u) == 0u) st_release_u32(&g_bgen[gid], my_gen + 1);
        else while (ld_acquire(&g_bgen[gid]) == my_gen) { }
        my_gen++;
    }
    __syncthreads();

    for (int s = 0; s < SN; s++) {
        int p = s & 1;
        int t = dir ? (SN - 1 - s) : s;

        {
            const __nv_bfloat16* hH = g_hbH + (size_t)((dir * 2 + p) * BN + bg * 16) * HN;
            const __nv_bfloat16* hL = g_hbL + (size_t)((dir * 2 + p) * BN + bg * 16) * HN;
            #pragma unroll
            for (int f = 0; f < 3; f++) {
                int i2 = tid + f * 256;
                int row = i2 / 48, c = i2 % 48;
                unsigned dh = (unsigned)__cvta_generic_to_shared(AhS + row * 392 + c * 8);
                asm volatile("cp.async.cg.shared.global [%0], [%1], 16;"
                             :: "r"(dh), "l"(hH + (size_t)row * HN + c * 8));
                unsigned dl = (unsigned)__cvta_generic_to_shared(AlS + row * 392 + c * 8);
                asm volatile("cp.async.cg.shared.global [%0], [%1], 16;"
                             :: "r"(dl), "l"(hL + (size_t)row * HN + c * 8));
            }
            asm volatile("cp.async.commit_group;");
        }

        float xp[4];
        if (cellv) {
            const float* xb = &g_xg[((size_t)(dir * SN + t) * BN + gb) * GN + gj];
            #pragma unroll
            for (int g2 = 0; g2 < 4; g2++) xp[g2] = xb[g2 * HN];
        }

        asm volatile("cp.async.wait_group 0;");
        __syncthreads();

        if (warp < 3) {
            const unsigned* Ah = (const unsigned*)AhS;
            const unsigned* Al = (const unsigned*)AlS;
            const unsigned* Bh = (const unsigned*)BhS;
            const unsigned* Bl = (const unsigned*)BlS;
            int baseA0 = g * 196, baseA1 = (g + 8) * 196;
            int baseB0 = (warp * 16 + g) * 196;
            int baseB1 = (warp * 16 + 8 + g) * 196;

            float d0[4] = {0.f, 0.f, 0.f, 0.f};
            float d1[4] = {0.f, 0.f, 0.f, 0.f};
            #pragma unroll 4
            for (int kt = 0; kt < 24; kt++) {
                int kk = kt * 8 + tig;
                unsigned ah[4] = {Ah[baseA0 + kk], Ah[baseA1 + kk],
                                  Ah[baseA0 + kk + 4], Ah[baseA1 + kk + 4]};
                unsigned al[4] = {Al[baseA0 + kk], Al[baseA1 + kk],
                                  Al[baseA0 + kk + 4], Al[baseA1 + kk + 4]};
                unsigned bh00 = Bh[baseB0 + kk], bh01 = Bh[baseB0 + kk + 4];
                unsigned bh10 = Bh[baseB1 + kk], bh11 = Bh[baseB1 + kk + 4];
                unsigned bl00 = Bl[baseB0 + kk], bl01 = Bl[baseB0 + kk + 4];
                unsigned bl10 = Bl[baseB1 + kk], bl11 = Bl[baseB1 + kk + 4];
                mma_bf16(d0, ah, bh00, bh01);
                mma_bf16(d0, ah, bl00, bl01);
                mma_bf16(d0, al, bh00, bh01);
                mma_bf16(d1, ah, bh10, bh11);
                mma_bf16(d1, ah, bl10, bl11);
                mma_bf16(d1, al, bh10, bh11);
            }
            int rb0 = warp * 16 + 2 * tig;
            P[(rb0 + 0) * 17 + g]     = d0[0];
            P[(rb0 + 1) * 17 + g]     = d0[1];
            P[(rb0 + 0) * 17 + g + 8] = d0[2];
            P[(rb0 + 1) * 17 + g + 8] = d0[3];
            int rb1 = rb0 + 8;
            P[(rb1 + 0) * 17 + g]     = d1[0];
            P[(rb1 + 1) * 17 + g]     = d1[1];
            P[(rb1 + 0) * 17 + g + 8] = d1[2];
            P[(rb1 + 1) * 17 + g + 8] = d1[3];
        }
        __syncthreads();

        float hv = 0.f;
        if (cellv) {
            bool valid = (t < sent_s[lb]);
            float g4[4];
            #pragma unroll
            for (int g2 = 0; g2 < 4; g2++) {
                int r = g2 * 12 + u;
                g4[g2] = P[r * 17 + lb] + (valid ? xp[g2] : bias_s[r]);
            }
            float ig = sig_fast(g4[0]), fg = sig_fast(g4[1]);
            float cg = tanh_fast(g4[2]), og = sig_fast(g4[3]);
            creg = fg * creg + ig * cg;
            hv = og * tanh_fast(creg);
            __nv_bfloat16 hh = __float2bfloat16(hv);
            size_t ho = (size_t)((dir * 2 + (p ^ 1)) * BN + gb) * HN + gj;
            g_hbH[ho] = hh;
            g_hbL[ho] = __float2bfloat16(hv - __bfloat162float(hh));
        }
        __syncthreads();

        if (tid == 0) {
            __threadfence();
            unsigned old = atom_add_acqrel(&g_bcnt[gid], 1u);
            if (((old + 1) & 31u) == 0u) st_release_u32(&g_bgen[gid], my_gen + 1);
        }
        if (cellv)
            g_lstm[((size_t)gb * SN + t) * (2 * HN) + dir * HN + gj] = hv;
        if (tid == 0) {
            while (ld_acquire(&g_bgen[gid]) == my_gen) { }
            my_gen++;
        }
        __syncthreads();
    }
}

// ---------------- K4: output linear (Wlin cached in smem, 16 rows/block) ----------
__global__ void __launch_bounds__(256) out_kernel(
    const float* __restrict__ Wlin, const float* __restrict__ blin,
    float* __restrict__ out)
{
    extern __shared__ float Wl[];
    int tid = threadIdx.x;
    int lane = tid & 31, w = tid >> 5;
    for (int idx = tid; idx < TN * 768; idx += 256) Wl[idx] = Wlin[idx];
    __syncthreads();

    int base = blockIdx.x * 16;
    #pragma unroll
    for (int rr = 0; rr < 2; rr++) {
        int row = base + w * 2 + rr;
        const float* src = g_lstm + (size_t)row * 768;
        float rs[24];
        #pragma unroll
        for (int i = 0; i < 24; i++) rs[i] = src[lane + 32 * i];
        for (int o = 0; o < TN; o++) {
            const float* wr = &Wl[o * 768];
            float s = 0.f;
            #pragma unroll
            for (int i = 0; i < 24; i++) s += rs[i] * wr[lane + 32 * i];
            #pragma unroll
            for (int off = 16; off; off >>= 1) s += __shfl_down_sync(0xffffffffu, s, off);
            if (lane == 0) out[(size_t)row * TN + o] = s + blin[o];
        }
    }
}

// ---------------- launch -----------------------------------------------------------
extern "C" void kernel_launch(void* const* d_in, const int* in_sizes, int n_in,
                              void* d_out, int out_size) {
    const float* hs   = (const float*)d_in[0];
    const float* h0   = (const float*)d_in[1];
    const float* c0   = (const float*)d_in[2];
    const float* Wihf = (const float*)d_in[3];
    const float* Whhf = (const float*)d_in[4];
    const float* bihf = (const float*)d_in[5];
    const float* bhhf = (const float*)d_in[6];
    const float* Wihb = (const float*)d_in[7];
    const float* Whhb = (const float*)d_in[8];
    const float* bihb = (const float*)d_in[9];
    const float* bhhb = (const float*)d_in[10];
    const float* Wlin = (const float*)d_in[11];
    const float* blin = (const float*)d_in[12];
    const void*  sid  = d_in[13];
    const void*  msk  = d_in[14];

    meta_kernel<<<BN, 256>>>(sid, msk);
    gather_kernel<<<dim3(SN, BN), 192>>>(hs, sid);
    wconv_kernel<<<(2 * GN * DN) / (256 * 4), 256>>>(Wihf, Wihb);
    wconv_hh_kernel<<<(2 * GN * HN) / (256 * 4), 256>>>(Whhf, Whhb);

    const int pj_smem = 2 * 15360 * 2;   // 61,440 B
    cudaFuncSetAttribute(projmma_kernel, cudaFuncAttributeMaxDynamicSharedMemorySize, pj_smem);
    projmma_kernel<<<dim3(GN / 128, SN / 64, 2 * BN), 256, pj_smem>>>(bihf, bhhf, bihb, bhhb);

    const int rec_smem = 103872;
    cudaFuncSetAttribute(lstm_kernel, cudaFuncAttributeMaxDynamicSharedMemorySize, rec_smem);
    lstm_kernel<<<256, 256, rec_smem>>>(bihf, bhhf, bihb, bhhb, h0, c0);

    const int out_smem = TN * 768 * 4;
    cudaFuncSetAttribute(out_kernel, cudaFuncAttributeMaxDynamicSharedMemorySize, out_smem);
    out_kernel<<<(BN * SN) / 16, 256, out_smem>>>(Wlin, blin, (float*)d_out);
}